// round 2
// baseline (speedup 1.0000x reference)
#include <cuda_runtime.h>
#include <cuda_bf16.h>
#include <math.h>

#define HIDDEN 2048
#define NH 16
#define NKV 4
#define HD 128
#define KVD (NKV * HD)      // 512
#define WINDOW 1024
#define BATCH 2
#define SEQ 2048
#define MTOK (BATCH * SEQ)  // 4096

// ---------------- scratch (static device globals; no allocation) ----------------
__device__ float g_q[MTOK * HIDDEN];     // 32 MB
__device__ float g_k[MTOK * KVD];        // 8 MB
__device__ float g_v[MTOK * KVD];        // 8 MB
__device__ float g_attn[MTOK * HIDDEN];  // 32 MB

// ---------------- SGEMM: C[M,N] = A[M,K] @ B[K,N] (+bias) -----------------------
// BM=BN=128, BK=8, 256 threads, 8x8 per thread. All dims divisible -> no guards.
template <bool BIAS>
__global__ __launch_bounds__(256) void sgemm_kernel(
    const float* __restrict__ A, const float* __restrict__ B,
    const float* __restrict__ bias, float* __restrict__ C,
    int N, int K)
{
    __shared__ float As[8][128];
    __shared__ float Bs[8][128];

    const int tid  = threadIdx.x;
    const int bm   = blockIdx.y * 128;
    const int bn   = blockIdx.x * 128;

    const int arow = tid >> 1;
    const int acol = (tid & 1) << 2;
    const int brow = tid >> 5;
    const int bcol = (tid & 31) << 2;
    const int tx   = tid & 15;
    const int ty   = tid >> 4;

    const float* Ap = A + (size_t)(bm + arow) * K + acol;
    const float* Bp = B + (size_t)brow * N + bn + bcol;

    float acc[8][8];
#pragma unroll
    for (int i = 0; i < 8; i++)
#pragma unroll
        for (int j = 0; j < 8; j++) acc[i][j] = 0.f;

    for (int k0 = 0; k0 < K; k0 += 8) {
        float4 a4 = *(const float4*)Ap;
        float4 b4 = *(const float4*)Bp;
        As[acol + 0][arow] = a4.x;
        As[acol + 1][arow] = a4.y;
        As[acol + 2][arow] = a4.z;
        As[acol + 3][arow] = a4.w;
        *(float4*)&Bs[brow][bcol] = b4;
        __syncthreads();

#pragma unroll
        for (int kk = 0; kk < 8; kk++) {
            float4 ra0 = *(const float4*)&As[kk][ty * 8];
            float4 ra1 = *(const float4*)&As[kk][ty * 8 + 4];
            float4 rb0 = *(const float4*)&Bs[kk][tx * 8];
            float4 rb1 = *(const float4*)&Bs[kk][tx * 8 + 4];
            float ra[8] = {ra0.x, ra0.y, ra0.z, ra0.w, ra1.x, ra1.y, ra1.z, ra1.w};
            float rb[8] = {rb0.x, rb0.y, rb0.z, rb0.w, rb1.x, rb1.y, rb1.z, rb1.w};
#pragma unroll
            for (int i = 0; i < 8; i++)
#pragma unroll
                for (int j = 0; j < 8; j++) acc[i][j] += ra[i] * rb[j];
        }
        __syncthreads();
        Ap += 8;
        Bp += (size_t)8 * N;
    }

#pragma unroll
    for (int i = 0; i < 8; i++) {
        size_t row = (size_t)(bm + ty * 8 + i);
        float* Cp = C + row * N + bn + tx * 8;
#pragma unroll
        for (int j = 0; j < 8; j += 4) {
            float4 vv;
            vv.x = acc[i][j + 0];
            vv.y = acc[i][j + 1];
            vv.z = acc[i][j + 2];
            vv.w = acc[i][j + 3];
            if (BIAS) {
                const float* bp = bias + bn + tx * 8 + j;
                vv.x += bp[0]; vv.y += bp[1]; vv.z += bp[2]; vv.w += bp[3];
            }
            *(float4*)(Cp + j) = vv;
        }
    }
}

// ---------------- RoPE on q (16 heads) and k (4 heads) --------------------------
// Positions are known exactly: position_ids = broadcast(arange(SEQ)) -> pos = tok % SEQ.
// (Avoids int32-vs-int64 ambiguity of the position_ids input buffer.)
__global__ void rope_kernel(float* __restrict__ q, float* __restrict__ k)
{
    int idx = blockIdx.x * blockDim.x + threadIdx.x;
    const int total = MTOK * (NH + NKV) * (HD / 2);
    if (idx >= total) return;
    int i    = idx & 63;          // rotary pair index 0..63
    int rest = idx >> 6;
    int head = rest % (NH + NKV);
    int tok  = rest / (NH + NKV);

    double pos = (double)(tok % SEQ);
    // inv_freq = 10000^(-i/64)
    double inv = exp(-(double)i * (9.210340371976184 / 64.0));
    double ang = pos * inv;
    float c = (float)cos(ang), s = (float)sin(ang);

    float* base = (head < NH) ? (q + (size_t)tok * HIDDEN + head * HD)
                              : (k + (size_t)tok * KVD + (head - NH) * HD);
    float x1 = base[i];
    float x2 = base[i + 64];
    base[i]      = x1 * c - x2 * s;
    base[i + 64] = x2 * c + x1 * s;
}

// ---------------- Flash attention (sliding window, GQA) -------------------------
// grid: (SEQ/64, NH, BATCH); 256 threads. Each thread: row r = tid/4, group g = tid%4,
// owns 32 output dims c = g*32 + [0,32) and 16 score cols j = 4*jj + g.
#define QPAD 132
#define FLASH_SMEM ((3 * 64 * QPAD + 64 * 65) * 4)

__global__ __launch_bounds__(256) void flash_kernel(
    const float* __restrict__ q, const float* __restrict__ k,
    const float* __restrict__ v, float* __restrict__ o_out)
{
    extern __shared__ float sm[];
    float* Qs = sm;                       // 64 x 132
    float* Ks = Qs + 64 * QPAD;           // 64 x 132
    float* Vs = Ks + 64 * QPAD;           // 64 x 132
    float* Ps = Vs + 64 * QPAD;           // 64 x 65

    const int qb  = blockIdx.x;
    const int h   = blockIdx.y;
    const int b   = blockIdx.z;
    const int kvh = h >> 2;
    const int tid = threadIdx.x;
    const int r   = tid >> 2;
    const int g   = tid & 3;
    const int q0  = qb * 64;
    const int qpos = q0 + r;
    const float scale = 0.08838834764831845f;  // 1/sqrt(128)

    // load Q tile (64 x 128)
    for (int idx = tid; idx < 64 * 32; idx += 256) {
        int row = idx >> 5, c4 = (idx & 31) << 2;
        float4 val = *(const float4*)&q[(size_t)(b * SEQ + q0 + row) * HIDDEN + h * HD + c4];
        *(float4*)&Qs[row * QPAD + c4] = val;
    }

    float oacc[32];
#pragma unroll
    for (int i = 0; i < 32; i++) oacc[i] = 0.f;
    float m_run = -1e30f, l_run = 0.f;

    int kstart = q0 - (WINDOW - 1);
    if (kstart < 0) kstart = 0;
    const int kb0 = (kstart >> 6) << 6;

    for (int kb = kb0; kb <= q0; kb += 64) {
        __syncthreads();  // previous tile fully consumed
        for (int idx = tid; idx < 64 * 32; idx += 256) {
            int row = idx >> 5, c4 = (idx & 31) << 2;
            size_t goff = (size_t)(b * SEQ + kb + row) * KVD + kvh * HD + c4;
            *(float4*)&Ks[row * QPAD + c4] = *(const float4*)&k[goff];
            *(float4*)&Vs[row * QPAD + c4] = *(const float4*)&v[goff];
        }
        __syncthreads();

        // scores for this row's 16 columns j = 4*jj + g
        float p[16];
        float smax = -1e30f;
        const bool rowvalid = (kb <= qpos) && (kb + 63 > qpos - WINDOW);
        if (rowvalid) {
            float accs[16];
#pragma unroll
            for (int jj = 0; jj < 16; jj++) accs[jj] = 0.f;
#pragma unroll
            for (int kk = 0; kk < 128; kk += 4) {
                float4 qv = *(const float4*)&Qs[r * QPAD + kk];
#pragma unroll
                for (int jj = 0; jj < 16; jj++) {
                    float4 kv = *(const float4*)&Ks[((jj << 2) | g) * QPAD + kk];
                    accs[jj] += qv.x * kv.x + qv.y * kv.y + qv.z * kv.z + qv.w * kv.w;
                }
            }
#pragma unroll
            for (int jj = 0; jj < 16; jj++) {
                int kpos = kb + ((jj << 2) | g);
                bool ok = (kpos <= qpos) && (kpos > qpos - WINDOW);
                p[jj] = ok ? accs[jj] * scale : -1e30f;
                smax = fmaxf(smax, p[jj]);
            }
        } else {
#pragma unroll
            for (int jj = 0; jj < 16; jj++) p[jj] = -1e30f;
        }

        // row max over the 4 lanes of this row
        smax = fmaxf(smax, __shfl_xor_sync(0xffffffffu, smax, 1));
        smax = fmaxf(smax, __shfl_xor_sync(0xffffffffu, smax, 2));
        float m_new = fmaxf(m_run, smax);

        float corr, psum = 0.f;
        if (m_new < -1e29f) {  // nothing valid yet for this row
            corr = 1.f;
#pragma unroll
            for (int jj = 0; jj < 16; jj++) p[jj] = 0.f;
        } else {
            corr = __expf(m_run - m_new);
#pragma unroll
            for (int jj = 0; jj < 16; jj++) {
                p[jj] = __expf(p[jj] - m_new);
                psum += p[jj];
            }
        }
        psum += __shfl_xor_sync(0xffffffffu, psum, 1);
        psum += __shfl_xor_sync(0xffffffffu, psum, 2);
        l_run = l_run * corr + psum;
        m_run = m_new;

#pragma unroll
        for (int jj = 0; jj < 16; jj++) Ps[r * 65 + ((jj << 2) | g)] = p[jj];
#pragma unroll
        for (int i = 0; i < 32; i++) oacc[i] *= corr;
        __syncwarp();

        // O += P @ V  (this thread: 32 dims c = g*32 + [0,32))
#pragma unroll 4
        for (int j = 0; j < 64; j++) {
            float pj = Ps[r * 65 + j];
            const float4* Vrow = (const float4*)&Vs[j * QPAD + (g << 5)];
#pragma unroll
            for (int ii = 0; ii < 8; ii++) {
                float4 vv = Vrow[ii];
                oacc[ii * 4 + 0] += pj * vv.x;
                oacc[ii * 4 + 1] += pj * vv.y;
                oacc[ii * 4 + 2] += pj * vv.z;
                oacc[ii * 4 + 3] += pj * vv.w;
            }
        }
    }

    float inv = 1.f / l_run;
    float* Op = o_out + (size_t)(b * SEQ + qpos) * HIDDEN + h * HD + (g << 5);
#pragma unroll
    for (int ii = 0; ii < 8; ii++) {
        float4 vv;
        vv.x = oacc[ii * 4 + 0] * inv;
        vv.y = oacc[ii * 4 + 1] * inv;
        vv.z = oacc[ii * 4 + 2] * inv;
        vv.w = oacc[ii * 4 + 3] * inv;
        *(float4*)(Op + ii * 4) = vv;
    }
}

// ---------------- launch ---------------------------------------------------------
extern "C" void kernel_launch(void* const* d_in, const int* in_sizes, int n_in,
                              void* d_out, int out_size)
{
    const float*     hs  = (const float*)d_in[0];
    const float*     Wq  = (const float*)d_in[2];
    const float*     bq  = (const float*)d_in[3];
    const float*     Wk  = (const float*)d_in[4];
    const float*     bk  = (const float*)d_in[5];
    const float*     Wv  = (const float*)d_in[6];
    const float*     bv  = (const float*)d_in[7];
    const float*     Wo  = (const float*)d_in[8];
    float*           out = (float*)d_out;

    void *pq, *pk, *pv, *pa;
    cudaGetSymbolAddress(&pq, g_q);
    cudaGetSymbolAddress(&pk, g_k);
    cudaGetSymbolAddress(&pv, g_v);
    cudaGetSymbolAddress(&pa, g_attn);
    float* qb = (float*)pq;
    float* kb = (float*)pk;
    float* vb = (float*)pv;
    float* ab = (float*)pa;

    dim3 blk(256);
    // QKV projections
    sgemm_kernel<true><<<dim3(HIDDEN / 128, MTOK / 128), blk>>>(hs, Wq, bq, qb, HIDDEN, HIDDEN);
    sgemm_kernel<true><<<dim3(KVD / 128, MTOK / 128), blk>>>(hs, Wk, bk, kb, KVD, HIDDEN);
    sgemm_kernel<true><<<dim3(KVD / 128, MTOK / 128), blk>>>(hs, Wv, bv, vb, KVD, HIDDEN);

    // RoPE
    {
        int total = MTOK * (NH + NKV) * (HD / 2);
        rope_kernel<<<(total + 255) / 256, 256>>>(qb, kb);
    }

    // Flash attention
    cudaFuncSetAttribute(flash_kernel, cudaFuncAttributeMaxDynamicSharedMemorySize, FLASH_SMEM);
    flash_kernel<<<dim3(SEQ / 64, NH, BATCH), 256, FLASH_SMEM>>>(qb, kb, vb, ab);

    // Output projection
    sgemm_kernel<false><<<dim3(HIDDEN / 128, MTOK / 128), blk>>>(ab, Wo, nullptr, out, HIDDEN, HIDDEN);
}

// round 4
// speedup vs baseline: 1.4802x; 1.4802x over previous
#include <cuda_runtime.h>
#include <cuda_bf16.h>
#include <math.h>
#include <cstdint>

#define HIDDEN 2048
#define NH 16
#define NKV 4
#define HD 128
#define KVD 512
#define WINDOW 1024
#define BATCH 2
#define SEQ 2048
#define MTOK 4096
#define GK 2048

// ---------------- scratch (static device globals; no allocation) ----------------
__device__ float g_q[MTOK * HIDDEN];
__device__ float g_k[MTOK * KVD];
__device__ float g_v[MTOK * KVD];
__device__ float g_attn[MTOK * HIDDEN];
__device__ __nv_bfloat16 g_xh[MTOK * GK], g_xl[MTOK * GK];          // activations split
__device__ __nv_bfloat16 g_wqh[HIDDEN * GK], g_wql[HIDDEN * GK];    // W^T [N,K] splits
__device__ __nv_bfloat16 g_wkh[KVD * GK],    g_wkl[KVD * GK];
__device__ __nv_bfloat16 g_wvh[KVD * GK],    g_wvl[KVD * GK];
__device__ __nv_bfloat16 g_woh[HIDDEN * GK], g_wol[HIDDEN * GK];
__device__ float g_cos[SEQ * 64], g_sin[SEQ * 64];

// ---------------- helpers --------------------------------------------------------
__device__ __forceinline__ uint32_t smem_u32(const void* p) {
    uint32_t a;
    asm("{ .reg .u64 t; cvta.to.shared.u64 t, %1; cvt.u32.u64 %0, t; }" : "=r"(a) : "l"(p));
    return a;
}
__device__ __forceinline__ void ldmx4(uint32_t* r, uint32_t addr) {
    asm volatile("ldmatrix.sync.aligned.m8n8.x4.shared.b16 {%0,%1,%2,%3}, [%4];"
                 : "=r"(r[0]), "=r"(r[1]), "=r"(r[2]), "=r"(r[3]) : "r"(addr));
}
__device__ __forceinline__ void mma16816(float* d, const uint32_t* a, const uint32_t* b) {
    asm volatile(
        "mma.sync.aligned.m16n8k16.row.col.f32.bf16.bf16.f32 "
        "{%0,%1,%2,%3}, {%4,%5,%6,%7}, {%8,%9}, {%0,%1,%2,%3};"
        : "+f"(d[0]), "+f"(d[1]), "+f"(d[2]), "+f"(d[3])
        : "r"(a[0]), "r"(a[1]), "r"(a[2]), "r"(a[3]), "r"(b[0]), "r"(b[1]));
}

#define SMEM_GEMM (2 * 4 * 16384)   // 2 stages x (Ah,Al,Bh,Bl) x 16KB = 128KB

// ---------------- bf16x2-split GEMM via mma.sync ---------------------------------
// C[M=4096, N] = (Ah+Al)[M,K=2048] @ (Bh+Bl)^T, B stored [N,K]. 3 mma passes.
__global__ __launch_bounds__(256, 1) void gemm_mma(
    const __nv_bfloat16* __restrict__ Ah, const __nv_bfloat16* __restrict__ Al,
    const __nv_bfloat16* __restrict__ Bh, const __nv_bfloat16* __restrict__ Bl,
    const float* __restrict__ bias, float* __restrict__ C, int N)
{
    extern __shared__ __align__(128) char smem[];
    const uint32_t sb = smem_u32(smem);
    const int tid  = threadIdx.x;
    const int lane = tid & 31;
    const int wid  = tid >> 5;
    const int wm   = wid >> 2;   // 0..1 : 64-row slab
    const int wn   = wid & 3;    // 0..3 : 32-col slab
    const int bn   = blockIdx.x * 128;
    const int bm   = blockIdx.y * 128;

    const __nv_bfloat16* srcs[4] = {
        Ah + (size_t)bm * GK, Al + (size_t)bm * GK,
        Bh + (size_t)bn * GK, Bl + (size_t)bn * GK };
    const int rr = tid >> 3, cc = tid & 7;

    // ldmatrix lane addressing constants
    const int idx8    = lane & 7;
    const int a_moff  = ((lane >> 3) & 1) * 8;
    const int a_coff  = lane >> 4;          // 0..1
    const int b_noff  = (lane >> 4) * 8;
    const int b_coff  = (lane >> 3) & 1;

    float acc[4][4][4];
#pragma unroll
    for (int i = 0; i < 4; i++)
#pragma unroll
        for (int j = 0; j < 4; j++)
#pragma unroll
            for (int e = 0; e < 4; e++) acc[i][j][e] = 0.f;

    // async stage: (Ah,Al,Bh,Bl) tiles, each 128 rows x 64 bf16 SW128-swizzled
#define ISSUE(c, buf)                                                              \
    {                                                                              \
        const int k0_ = (c) * 64;                                                  \
        const uint32_t st_ = sb + (buf) * 65536;                                   \
        _Pragma("unroll") for (int t = 0; t < 4; t++) {                            \
            const __nv_bfloat16* bp = srcs[t] + k0_ + cc * 8;                      \
            _Pragma("unroll") for (int j = 0; j < 4; j++) {                        \
                int r_ = rr + 32 * j;                                              \
                int byte_ = r_ * 128 + cc * 16;                                    \
                uint32_t dst_ = st_ + t * 16384 + (byte_ ^ ((byte_ >> 3) & 0x70)); \
                const void* s_ = bp + (size_t)r_ * GK;                             \
                asm volatile("cp.async.cg.shared.global [%0], [%1], 16;"           \
                             :: "r"(dst_), "l"(s_) : "memory");                    \
            }                                                                      \
        }                                                                          \
        asm volatile("cp.async.commit_group;" ::: "memory");                       \
    }

    ISSUE(0, 0);
    ISSUE(1, 1);

    for (int c = 0; c < 32; c++) {
        if (c < 31) asm volatile("cp.async.wait_group 1;" ::: "memory");
        else        asm volatile("cp.async.wait_group 0;" ::: "memory");
        __syncthreads();
        const uint32_t st = sb + (c & 1) * 65536;

#pragma unroll
        for (int ks = 0; ks < 4; ks++) {
            uint32_t ah[4][4], al[4][4], bh[2][4], bl[2][4];
            const int chA = ks * 2 + a_coff;
            const int chB = ks * 2 + b_coff;
#pragma unroll
            for (int mt = 0; mt < 4; mt++) {
                int row = wm * 64 + mt * 16 + a_moff + idx8;
                uint32_t off = row * 128 + ((chA ^ (row & 7)) << 4);
                ldmx4(ah[mt], st + off);            // Ah tile at +0
                ldmx4(al[mt], st + 16384 + off);    // Al tile
            }
#pragma unroll
            for (int h = 0; h < 2; h++) {
                int row = wn * 32 + h * 16 + b_noff + idx8;
                uint32_t off = row * 128 + ((chB ^ (row & 7)) << 4);
                ldmx4(bh[h], st + 32768 + off);     // Bh tile
                ldmx4(bl[h], st + 49152 + off);     // Bl tile
            }
#pragma unroll
            for (int mt = 0; mt < 4; mt++)
#pragma unroll
                for (int nt = 0; nt < 4; nt++) {
                    const uint32_t* ph = &bh[nt >> 1][(nt & 1) * 2];
                    const uint32_t* pl = &bl[nt >> 1][(nt & 1) * 2];
                    mma16816(acc[mt][nt], ah[mt], ph);
                    mma16816(acc[mt][nt], ah[mt], pl);
                    mma16816(acc[mt][nt], al[mt], ph);
                }
        }
        __syncthreads();
        if (c + 2 < 32) ISSUE(c + 2, c & 1);
    }

    // epilogue
    const int erow = bm + wm * 64 + (lane >> 2);
    const int ecol = bn + wn * 32 + (lane & 3) * 2;
#pragma unroll
    for (int mt = 0; mt < 4; mt++)
#pragma unroll
        for (int nt = 0; nt < 4; nt++) {
            int row = erow + mt * 16;
            int col = ecol + nt * 8;
            float b0 = 0.f, b1 = 0.f;
            if (bias) { b0 = bias[col]; b1 = bias[col + 1]; }
            float2 v0 = make_float2(acc[mt][nt][0] + b0, acc[mt][nt][1] + b1);
            float2 v1 = make_float2(acc[mt][nt][2] + b0, acc[mt][nt][3] + b1);
            *(float2*)(C + (size_t)row * N + col)       = v0;
            *(float2*)(C + (size_t)(row + 8) * N + col) = v1;
        }
}

// ---------------- fp32 -> bf16 hi/lo split ---------------------------------------
__global__ void split_fp32(const float4* __restrict__ X, __nv_bfloat16* __restrict__ H,
                           __nv_bfloat16* __restrict__ L, int n4)
{
    int i = blockIdx.x * blockDim.x + threadIdx.x;
    if (i >= n4) return;
    float4 v = X[i];
    float vv[4] = {v.x, v.y, v.z, v.w};
    uint32_t hp[2], lp[2];
#pragma unroll
    for (int p = 0; p < 2; p++) {
        __nv_bfloat16 h0 = __float2bfloat16(vv[p * 2 + 0]);
        __nv_bfloat16 h1 = __float2bfloat16(vv[p * 2 + 1]);
        __nv_bfloat16 l0 = __float2bfloat16(vv[p * 2 + 0] - __bfloat162float(h0));
        __nv_bfloat16 l1 = __float2bfloat16(vv[p * 2 + 1] - __bfloat162float(h1));
        hp[p] = (uint32_t)__bfloat16_as_ushort(h0) | ((uint32_t)__bfloat16_as_ushort(h1) << 16);
        lp[p] = (uint32_t)__bfloat16_as_ushort(l0) | ((uint32_t)__bfloat16_as_ushort(l1) << 16);
    }
    *(uint2*)(H + (size_t)i * 4) = make_uint2(hp[0], hp[1]);
    *(uint2*)(L + (size_t)i * 4) = make_uint2(lp[0], lp[1]);
}

// ---------------- W [2048,N] fp32 -> W^T [N,2048] bf16 hi/lo ----------------------
__global__ void transp_split(const float* __restrict__ W, __nv_bfloat16* __restrict__ H,
                             __nv_bfloat16* __restrict__ L, int N)
{
    __shared__ float t[32][33];
    int n0 = blockIdx.x * 32, k0 = blockIdx.y * 32;
    int tx = threadIdx.x, ty = threadIdx.y;  // 32 x 8
#pragma unroll
    for (int i = 0; i < 32; i += 8)
        t[ty + i][tx] = W[(size_t)(k0 + ty + i) * N + n0 + tx];
    __syncthreads();
#pragma unroll
    for (int i = 0; i < 32; i += 8) {
        float v = t[tx][ty + i];
        __nv_bfloat16 h = __float2bfloat16(v);
        __nv_bfloat16 l = __float2bfloat16(v - __bfloat162float(h));
        size_t o = (size_t)(n0 + ty + i) * GK + k0 + tx;
        H[o] = h; L[o] = l;
    }
}

// ---------------- RoPE: fp64 table (tiny) + fp32 apply ---------------------------
__global__ void rope_table()
{
    int idx = blockIdx.x * blockDim.x + threadIdx.x;
    if (idx >= SEQ * 64) return;
    int pos = idx >> 6, i = idx & 63;
    double ang = (double)pos * exp(-(double)i * (9.210340371976184 / 64.0));
    g_cos[idx] = (float)cos(ang);
    g_sin[idx] = (float)sin(ang);
}
__global__ void rope_apply(float* __restrict__ q, float* __restrict__ k)
{
    int idx = blockIdx.x * blockDim.x + threadIdx.x;
    const int total = MTOK * (NH + NKV) * 64;
    if (idx >= total) return;
    int i = idx & 63;
    int rest = idx >> 6;
    int head = rest % (NH + NKV);
    int tok = rest / (NH + NKV);
    int pos = tok & (SEQ - 1);
    float c = g_cos[pos * 64 + i], s = g_sin[pos * 64 + i];
    float* base = (head < NH) ? (q + (size_t)tok * HIDDEN + head * HD)
                              : (k + (size_t)tok * KVD + (head - NH) * HD);
    float x1 = base[i];
    float x2 = base[i + 64];
    base[i]      = x1 * c - x2 * s;
    base[i + 64] = x2 * c + x1 * s;
}

// ---------------- Flash attention (sliding window, GQA) --------------------------
#define QPAD 132
#define FLASH_SMEM ((3 * 64 * QPAD + 64 * 65) * 4)

__global__ __launch_bounds__(256) void flash_kernel(
    const float* __restrict__ q, const float* __restrict__ k,
    const float* __restrict__ v, float* __restrict__ o_out)
{
    extern __shared__ float sm[];
    float* Qs = sm;
    float* Ks = Qs + 64 * QPAD;
    float* Vs = Ks + 64 * QPAD;
    float* Ps = Vs + 64 * QPAD;

    const int qb  = blockIdx.x;
    const int h   = blockIdx.y;
    const int b   = blockIdx.z;
    const int kvh = h >> 2;
    const int tid = threadIdx.x;
    const int r   = tid >> 2;
    const int g   = tid & 3;
    const int q0  = qb * 64;
    const int qpos = q0 + r;
    const float scale = 0.08838834764831845f;

    for (int idx = tid; idx < 64 * 32; idx += 256) {
        int row = idx >> 5, c4 = (idx & 31) << 2;
        float4 val = *(const float4*)&q[(size_t)(b * SEQ + q0 + row) * HIDDEN + h * HD + c4];
        *(float4*)&Qs[row * QPAD + c4] = val;
    }

    float oacc[32];
#pragma unroll
    for (int i = 0; i < 32; i++) oacc[i] = 0.f;
    float m_run = -1e30f, l_run = 0.f;

    int kstart = q0 - (WINDOW - 1);
    if (kstart < 0) kstart = 0;
    const int kb0 = (kstart >> 6) << 6;

    for (int kb = kb0; kb <= q0; kb += 64) {
        __syncthreads();
        for (int idx = tid; idx < 64 * 32; idx += 256) {
            int row = idx >> 5, c4 = (idx & 31) << 2;
            size_t goff = (size_t)(b * SEQ + kb + row) * KVD + kvh * HD + c4;
            *(float4*)&Ks[row * QPAD + c4] = *(const float4*)&k[goff];
            *(float4*)&Vs[row * QPAD + c4] = *(const float4*)&v[goff];
        }
        __syncthreads();

        float p[16];
        float smax = -1e30f;
        const bool rowvalid = (kb <= qpos) && (kb + 63 > qpos - WINDOW);
        if (rowvalid) {
            float accs[16];
#pragma unroll
            for (int jj = 0; jj < 16; jj++) accs[jj] = 0.f;
#pragma unroll
            for (int kk = 0; kk < 128; kk += 4) {
                float4 qv = *(const float4*)&Qs[r * QPAD + kk];
#pragma unroll
                for (int jj = 0; jj < 16; jj++) {
                    float4 kv = *(const float4*)&Ks[((jj << 2) | g) * QPAD + kk];
                    accs[jj] += qv.x * kv.x + qv.y * kv.y + qv.z * kv.z + qv.w * kv.w;
                }
            }
#pragma unroll
            for (int jj = 0; jj < 16; jj++) {
                int kpos = kb + ((jj << 2) | g);
                bool ok = (kpos <= qpos) && (kpos > qpos - WINDOW);
                p[jj] = ok ? accs[jj] * scale : -1e30f;
                smax = fmaxf(smax, p[jj]);
            }
        } else {
#pragma unroll
            for (int jj = 0; jj < 16; jj++) p[jj] = -1e30f;
        }

        smax = fmaxf(smax, __shfl_xor_sync(0xffffffffu, smax, 1));
        smax = fmaxf(smax, __shfl_xor_sync(0xffffffffu, smax, 2));
        float m_new = fmaxf(m_run, smax);

        float corr, psum = 0.f;
        if (m_new < -1e29f) {
            corr = 1.f;
#pragma unroll
            for (int jj = 0; jj < 16; jj++) p[jj] = 0.f;
        } else {
            corr = __expf(m_run - m_new);
#pragma unroll
            for (int jj = 0; jj < 16; jj++) {
                p[jj] = __expf(p[jj] - m_new);
                psum += p[jj];
            }
        }
        psum += __shfl_xor_sync(0xffffffffu, psum, 1);
        psum += __shfl_xor_sync(0xffffffffu, psum, 2);
        l_run = l_run * corr + psum;
        m_run = m_new;

#pragma unroll
        for (int jj = 0; jj < 16; jj++) Ps[r * 65 + ((jj << 2) | g)] = p[jj];
#pragma unroll
        for (int i = 0; i < 32; i++) oacc[i] *= corr;
        __syncwarp();

#pragma unroll 4
        for (int j = 0; j < 64; j++) {
            float pj = Ps[r * 65 + j];
            const float4* Vrow = (const float4*)&Vs[j * QPAD + (g << 5)];
#pragma unroll
            for (int ii = 0; ii < 8; ii++) {
                float4 vv = Vrow[ii];
                oacc[ii * 4 + 0] += pj * vv.x;
                oacc[ii * 4 + 1] += pj * vv.y;
                oacc[ii * 4 + 2] += pj * vv.z;
                oacc[ii * 4 + 3] += pj * vv.w;
            }
        }
    }

    float inv = 1.f / l_run;
    float* Op = o_out + (size_t)(b * SEQ + qpos) * HIDDEN + h * HD + (g << 5);
#pragma unroll
    for (int ii = 0; ii < 8; ii++) {
        float4 vv;
        vv.x = oacc[ii * 4 + 0] * inv;
        vv.y = oacc[ii * 4 + 1] * inv;
        vv.z = oacc[ii * 4 + 2] * inv;
        vv.w = oacc[ii * 4 + 3] * inv;
        *(float4*)(Op + ii * 4) = vv;
    }
}

// ---------------- launch ----------------------------------------------------------
extern "C" void kernel_launch(void* const* d_in, const int* in_sizes, int n_in,
                              void* d_out, int out_size)
{
    const float* hs = (const float*)d_in[0];
    const float* Wq = (const float*)d_in[2];
    const float* bq = (const float*)d_in[3];
    const float* Wk = (const float*)d_in[4];
    const float* bk = (const float*)d_in[5];
    const float* Wv = (const float*)d_in[6];
    const float* bv = (const float*)d_in[7];
    const float* Wo = (const float*)d_in[8];
    float* out = (float*)d_out;

    void *pq, *pk, *pv, *pa, *pxh, *pxl, *pwqh, *pwql, *pwkh, *pwkl, *pwvh, *pwvl, *pwoh, *pwol;
    cudaGetSymbolAddress(&pq, g_q);
    cudaGetSymbolAddress(&pk, g_k);
    cudaGetSymbolAddress(&pv, g_v);
    cudaGetSymbolAddress(&pa, g_attn);
    cudaGetSymbolAddress(&pxh, g_xh);
    cudaGetSymbolAddress(&pxl, g_xl);
    cudaGetSymbolAddress(&pwqh, g_wqh);
    cudaGetSymbolAddress(&pwql, g_wql);
    cudaGetSymbolAddress(&pwkh, g_wkh);
    cudaGetSymbolAddress(&pwkl, g_wkl);
    cudaGetSymbolAddress(&pwvh, g_wvh);
    cudaGetSymbolAddress(&pwvl, g_wvl);
    cudaGetSymbolAddress(&pwoh, g_woh);
    cudaGetSymbolAddress(&pwol, g_wol);
    float* qb = (float*)pq;
    float* kb2 = (float*)pk;
    float* vb = (float*)pv;
    float* ab = (float*)pa;
    __nv_bfloat16* xh = (__nv_bfloat16*)pxh;
    __nv_bfloat16* xl = (__nv_bfloat16*)pxl;

    cudaFuncSetAttribute(gemm_mma, cudaFuncAttributeMaxDynamicSharedMemorySize, SMEM_GEMM);
    cudaFuncSetAttribute(flash_kernel, cudaFuncAttributeMaxDynamicSharedMemorySize, FLASH_SMEM);

    const int n4 = MTOK * GK / 4;
    dim3 tb(32, 8);

    split_fp32<<<(n4 + 255) / 256, 256>>>((const float4*)hs, xh, xl, n4);
    transp_split<<<dim3(HIDDEN / 32, GK / 32), tb>>>(Wq, (__nv_bfloat16*)pwqh, (__nv_bfloat16*)pwql, HIDDEN);
    transp_split<<<dim3(KVD / 32, GK / 32), tb>>>(Wk, (__nv_bfloat16*)pwkh, (__nv_bfloat16*)pwkl, KVD);
    transp_split<<<dim3(KVD / 32, GK / 32), tb>>>(Wv, (__nv_bfloat16*)pwvh, (__nv_bfloat16*)pwvl, KVD);
    transp_split<<<dim3(HIDDEN / 32, GK / 32), tb>>>(Wo, (__nv_bfloat16*)pwoh, (__nv_bfloat16*)pwol, HIDDEN);

    gemm_mma<<<dim3(HIDDEN / 128, MTOK / 128), 256, SMEM_GEMM>>>(
        xh, xl, (__nv_bfloat16*)pwqh, (__nv_bfloat16*)pwql, bq, qb, HIDDEN);
    gemm_mma<<<dim3(KVD / 128, MTOK / 128), 256, SMEM_GEMM>>>(
        xh, xl, (__nv_bfloat16*)pwkh, (__nv_bfloat16*)pwkl, bk, kb2, KVD);
    gemm_mma<<<dim3(KVD / 128, MTOK / 128), 256, SMEM_GEMM>>>(
        xh, xl, (__nv_bfloat16*)pwvh, (__nv_bfloat16*)pwvl, bv, vb, KVD);

    rope_table<<<(SEQ * 64 + 255) / 256, 256>>>();
    {
        int total = MTOK * (NH + NKV) * 64;
        rope_apply<<<(total + 255) / 256, 256>>>(qb, kb2);
    }

    flash_kernel<<<dim3(SEQ / 64, NH, BATCH), 256, FLASH_SMEM>>>(qb, kb2, vb, ab);

    split_fp32<<<(n4 + 255) / 256, 256>>>((const float4*)ab, xh, xl, n4);
    gemm_mma<<<dim3(HIDDEN / 128, MTOK / 128), 256, SMEM_GEMM>>>(
        xh, xl, (__nv_bfloat16*)pwoh, (__nv_bfloat16*)pwol, nullptr, out, HIDDEN);
}

// round 5
// speedup vs baseline: 7.6042x; 5.1375x over previous
#include <cuda_runtime.h>
#include <cuda_bf16.h>
#include <math.h>
#include <cstdint>

#define HIDDEN 2048
#define NH 16
#define NKV 4
#define HD 128
#define KVD 512
#define WINDOW 1024
#define BATCH 2
#define SEQ 2048
#define MTOK 4096
#define GK 2048

// ---------------- scratch (static device globals; no allocation) ----------------
__device__ float g_q[MTOK * HIDDEN];
__device__ float g_k[MTOK * KVD];
__device__ float g_v[MTOK * KVD];
__device__ __nv_bfloat16 g_xh[MTOK * GK], g_xl[MTOK * GK];          // act splits (hs, then attn out)
__device__ __nv_bfloat16 g_qh[MTOK * HIDDEN], g_ql[MTOK * HIDDEN];  // rotated Q splits
__device__ __nv_bfloat16 g_kh[MTOK * KVD], g_kl[MTOK * KVD];        // rotated K splits
__device__ __nv_bfloat16 g_vh[MTOK * KVD], g_vl[MTOK * KVD];        // V splits
__device__ __nv_bfloat16 g_wqh[HIDDEN * GK], g_wql[HIDDEN * GK];
__device__ __nv_bfloat16 g_wkh[KVD * GK],    g_wkl[KVD * GK];
__device__ __nv_bfloat16 g_wvh[KVD * GK],    g_wvl[KVD * GK];
__device__ __nv_bfloat16 g_woh[HIDDEN * GK], g_wol[HIDDEN * GK];
__device__ float g_cos[SEQ * 64], g_sin[SEQ * 64];

// ---------------- helpers --------------------------------------------------------
__device__ __forceinline__ uint32_t smem_u32(const void* p) {
    uint32_t a;
    asm("{ .reg .u64 t; cvta.to.shared.u64 t, %1; cvt.u32.u64 %0, t; }" : "=r"(a) : "l"(p));
    return a;
}
__device__ __forceinline__ void ldmx4(uint32_t* r, uint32_t addr) {
    asm volatile("ldmatrix.sync.aligned.m8n8.x4.shared.b16 {%0,%1,%2,%3}, [%4];"
                 : "=r"(r[0]), "=r"(r[1]), "=r"(r[2]), "=r"(r[3]) : "r"(addr));
}
__device__ __forceinline__ void ldmx4t(uint32_t* r, uint32_t addr) {
    asm volatile("ldmatrix.sync.aligned.m8n8.x4.trans.shared.b16 {%0,%1,%2,%3}, [%4];"
                 : "=r"(r[0]), "=r"(r[1]), "=r"(r[2]), "=r"(r[3]) : "r"(addr));
}
__device__ __forceinline__ void mma16816(float* d, const uint32_t* a, const uint32_t* b) {
    asm volatile(
        "mma.sync.aligned.m16n8k16.row.col.f32.bf16.bf16.f32 "
        "{%0,%1,%2,%3}, {%4,%5,%6,%7}, {%8,%9}, {%0,%1,%2,%3};"
        : "+f"(d[0]), "+f"(d[1]), "+f"(d[2]), "+f"(d[3])
        : "r"(a[0]), "r"(a[1]), "r"(a[2]), "r"(a[3]), "r"(b[0]), "r"(b[1]));
}
// pack (lo=a, hi=b) to bf16x2 (hpk) and the fp32-residual pair (lpk)
__device__ __forceinline__ void split2(float a, float b, uint32_t& hpk, uint32_t& lpk) {
    asm("cvt.rn.bf16x2.f32 %0, %1, %2;" : "=r"(hpk) : "f"(b), "f"(a));
    float fa = __uint_as_float(hpk << 16);
    float fb = __uint_as_float(hpk & 0xffff0000u);
    float ra = a - fa, rb = b - fb;
    asm("cvt.rn.bf16x2.f32 %0, %1, %2;" : "=r"(lpk) : "f"(rb), "f"(ra));
}
__device__ __forceinline__ void cpasync16(uint32_t dst, const void* src) {
    asm volatile("cp.async.cg.shared.global [%0], [%1], 16;" :: "r"(dst), "l"(src) : "memory");
}

#define SMEM_GEMM (3 * 4 * 16384)   // 3 stages x (Ah,Al,Bh,Bl) x 16KB = 192KB

// ---------------- bf16x2-split GEMM via mma.sync (3-stage pipeline) ---------------
__global__ __launch_bounds__(256, 1) void gemm_mma(
    const __nv_bfloat16* __restrict__ Ah, const __nv_bfloat16* __restrict__ Al,
    const __nv_bfloat16* __restrict__ Bh, const __nv_bfloat16* __restrict__ Bl,
    const float* __restrict__ bias, float* __restrict__ C, int N)
{
    extern __shared__ __align__(128) char smem[];
    const uint32_t sb = smem_u32(smem);
    const int tid  = threadIdx.x;
    const int lane = tid & 31;
    const int wid  = tid >> 5;
    const int wm   = wid >> 2;
    const int wn   = wid & 3;
    const int bn   = blockIdx.x * 128;
    const int bm   = blockIdx.y * 128;

    const __nv_bfloat16* srcs[4] = {
        Ah + (size_t)bm * GK, Al + (size_t)bm * GK,
        Bh + (size_t)bn * GK, Bl + (size_t)bn * GK };
    const int rr = tid >> 3, cc = tid & 7;

    const int idx8   = lane & 7;
    const int a_moff = ((lane >> 3) & 1) * 8;
    const int a_coff = lane >> 4;
    const int b_noff = (lane >> 4) * 8;
    const int b_coff = (lane >> 3) & 1;

    float acc[4][4][4];
#pragma unroll
    for (int i = 0; i < 4; i++)
#pragma unroll
        for (int j = 0; j < 4; j++)
#pragma unroll
            for (int e = 0; e < 4; e++) acc[i][j][e] = 0.f;

#define ISSUE(c, buf)                                                              \
    {                                                                              \
        const int k0_ = (c) * 64;                                                  \
        const uint32_t st_ = sb + (buf) * 65536;                                   \
        _Pragma("unroll") for (int t = 0; t < 4; t++) {                            \
            const __nv_bfloat16* bp = srcs[t] + k0_ + cc * 8;                      \
            _Pragma("unroll") for (int j = 0; j < 4; j++) {                        \
                int r_ = rr + 32 * j;                                              \
                int byte_ = r_ * 128 + cc * 16;                                    \
                uint32_t dst_ = st_ + t * 16384 + (byte_ ^ ((byte_ >> 3) & 0x70)); \
                cpasync16(dst_, bp + (size_t)r_ * GK);                             \
            }                                                                      \
        }                                                                          \
        asm volatile("cp.async.commit_group;" ::: "memory");                       \
    }

    ISSUE(0, 0);
    ISSUE(1, 1);
    ISSUE(2, 2);

    for (int c = 0; c < 32; c++) {
        if (c <= 29)      asm volatile("cp.async.wait_group 2;" ::: "memory");
        else if (c == 30) asm volatile("cp.async.wait_group 1;" ::: "memory");
        else              asm volatile("cp.async.wait_group 0;" ::: "memory");
        __syncthreads();
        const uint32_t st = sb + (c % 3) * 65536;

#pragma unroll
        for (int ks = 0; ks < 4; ks++) {
            uint32_t ah[4][4], al[4][4], bh[2][4], bl[2][4];
            const int chA = ks * 2 + a_coff;
            const int chB = ks * 2 + b_coff;
#pragma unroll
            for (int mt = 0; mt < 4; mt++) {
                int row = wm * 64 + mt * 16 + a_moff + idx8;
                uint32_t off = row * 128 + ((chA ^ (row & 7)) << 4);
                ldmx4(ah[mt], st + off);
                ldmx4(al[mt], st + 16384 + off);
            }
#pragma unroll
            for (int h = 0; h < 2; h++) {
                int row = wn * 32 + h * 16 + b_noff + idx8;
                uint32_t off = row * 128 + ((chB ^ (row & 7)) << 4);
                ldmx4(bh[h], st + 32768 + off);
                ldmx4(bl[h], st + 49152 + off);
            }
#pragma unroll
            for (int mt = 0; mt < 4; mt++)
#pragma unroll
                for (int nt = 0; nt < 4; nt++) {
                    const uint32_t* ph = &bh[nt >> 1][(nt & 1) * 2];
                    const uint32_t* pl = &bl[nt >> 1][(nt & 1) * 2];
                    mma16816(acc[mt][nt], ah[mt], ph);
                    mma16816(acc[mt][nt], ah[mt], pl);
                    mma16816(acc[mt][nt], al[mt], ph);
                }
        }
        __syncthreads();
        if (c + 3 < 32) ISSUE(c + 3, (c + 3) % 3);
    }

    const int erow = bm + wm * 64 + (lane >> 2);
    const int ecol = bn + wn * 32 + (lane & 3) * 2;
#pragma unroll
    for (int mt = 0; mt < 4; mt++)
#pragma unroll
        for (int nt = 0; nt < 4; nt++) {
            int row = erow + mt * 16;
            int col = ecol + nt * 8;
            float b0 = 0.f, b1 = 0.f;
            if (bias) { b0 = bias[col]; b1 = bias[col + 1]; }
            *(float2*)(C + (size_t)row * N + col)       = make_float2(acc[mt][nt][0] + b0, acc[mt][nt][1] + b1);
            *(float2*)(C + (size_t)(row + 8) * N + col) = make_float2(acc[mt][nt][2] + b0, acc[mt][nt][3] + b1);
        }
}

// ---------------- fp32 -> bf16 hi/lo split ---------------------------------------
__global__ void split_fp32(const float4* __restrict__ X, __nv_bfloat16* __restrict__ H,
                           __nv_bfloat16* __restrict__ L, int n4)
{
    int i = blockIdx.x * blockDim.x + threadIdx.x;
    if (i >= n4) return;
    float4 v = X[i];
    float vv[4] = {v.x, v.y, v.z, v.w};
    uint32_t hp[2], lp[2];
#pragma unroll
    for (int p = 0; p < 2; p++)
        split2(vv[p * 2 + 0], vv[p * 2 + 1], hp[p], lp[p]);
    *(uint2*)(H + (size_t)i * 4) = make_uint2(hp[0], hp[1]);
    *(uint2*)(L + (size_t)i * 4) = make_uint2(lp[0], lp[1]);
}

// ---------------- W [2048,N] fp32 -> W^T [N,2048] bf16 hi/lo ----------------------
__global__ void transp_split(const float* __restrict__ W, __nv_bfloat16* __restrict__ H,
                             __nv_bfloat16* __restrict__ L, int N)
{
    __shared__ float t[32][33];
    int n0 = blockIdx.x * 32, k0 = blockIdx.y * 32;
    int tx = threadIdx.x, ty = threadIdx.y;
#pragma unroll
    for (int i = 0; i < 32; i += 8)
        t[ty + i][tx] = W[(size_t)(k0 + ty + i) * N + n0 + tx];
    __syncthreads();
#pragma unroll
    for (int i = 0; i < 32; i += 8) {
        float v = t[tx][ty + i];
        __nv_bfloat16 h = __float2bfloat16(v);
        __nv_bfloat16 l = __float2bfloat16(v - __bfloat162float(h));
        size_t o = (size_t)(n0 + ty + i) * GK + k0 + tx;
        H[o] = h; L[o] = l;
    }
}

// ---------------- RoPE table + rope-and-split ------------------------------------
__global__ void rope_table()
{
    int idx = blockIdx.x * blockDim.x + threadIdx.x;
    if (idx >= SEQ * 64) return;
    int pos = idx >> 6, i = idx & 63;
    double ang = (double)pos * exp(-(double)i * (9.210340371976184 / 64.0));
    g_cos[idx] = (float)cos(ang);
    g_sin[idx] = (float)sin(ang);
}
__global__ void rope_split(const float* __restrict__ q, const float* __restrict__ k,
                           __nv_bfloat16* __restrict__ qh, __nv_bfloat16* __restrict__ ql,
                           __nv_bfloat16* __restrict__ kh, __nv_bfloat16* __restrict__ kl)
{
    int idx = blockIdx.x * blockDim.x + threadIdx.x;
    const int total = MTOK * (NH + NKV) * 64;
    if (idx >= total) return;
    int i = idx & 63, rest = idx >> 6;
    int head = rest % (NH + NKV), tok = rest / (NH + NKV);
    int pos = tok & (SEQ - 1);
    float c = g_cos[pos * 64 + i], s = g_sin[pos * 64 + i];
    const float* base; __nv_bfloat16 *oh, *ol;
    if (head < NH) {
        size_t off = (size_t)tok * HIDDEN + head * HD;
        base = q + off; oh = qh + off; ol = ql + off;
    } else {
        size_t off = (size_t)tok * KVD + (head - NH) * HD;
        base = k + off; oh = kh + off; ol = kl + off;
    }
    float x1 = base[i], x2 = base[i + 64];
    float y1 = x1 * c - x2 * s, y2 = x2 * c + x1 * s;
    __nv_bfloat16 h1 = __float2bfloat16(y1);
    __nv_bfloat16 h2 = __float2bfloat16(y2);
    oh[i]      = h1; ol[i]      = __float2bfloat16(y1 - __bfloat162float(h1));
    oh[i + 64] = h2; ol[i + 64] = __float2bfloat16(y2 - __bfloat162float(h2));
}

// ---------------- Flash attention via mma.sync (split bf16, FA2 style) -----------
// CTA: 64 q-rows, 128 threads (4 warps x 16 rows). K-block = 64 keys.
// smem: Qh Ql Kh Kl Vh Vl, each 64 rows x 128 bf16 (256B rows, swizzled 16B chunks).
#define FSMEM (6 * 16384)

__global__ __launch_bounds__(128, 2) void flash_mma(
    const __nv_bfloat16* __restrict__ Qh, const __nv_bfloat16* __restrict__ Ql,
    const __nv_bfloat16* __restrict__ Kh, const __nv_bfloat16* __restrict__ Kl,
    const __nv_bfloat16* __restrict__ Vh, const __nv_bfloat16* __restrict__ Vl,
    __nv_bfloat16* __restrict__ Oh, __nv_bfloat16* __restrict__ Ol)
{
    extern __shared__ __align__(128) char smem[];
    const uint32_t sb = smem_u32(smem);
    const uint32_t sQh = sb, sQl = sb + 16384, sKh = sb + 32768, sKl = sb + 49152,
                   sVh = sb + 65536, sVl = sb + 81920;
    const int qb = blockIdx.x, h = blockIdx.y, b = blockIdx.z;
    const int kvh = h >> 2;
    const int tid = threadIdx.x, lane = tid & 31, w = tid >> 5;
    const int q0 = qb * 64;
    const int l8 = lane & 7, grp = lane >> 3, qd = lane >> 2, ln4 = lane & 3;
    const float scale = 0.08838834764831845f;

    // ---- load Q tile (h+l) ----
#pragma unroll
    for (int i = 0; i < 8; i++) {
        int cid = tid + 128 * i;
        int row = cid >> 4, c = cid & 15;
        uint32_t soff = row * 256 + ((((c ^ row) & 7) | (c & 8)) << 4);
        size_t goff = (size_t)(b * SEQ + q0 + row) * HIDDEN + h * HD + c * 8;
        cpasync16(sQh + soff, Qh + goff);
        cpasync16(sQl + soff, Ql + goff);
    }
    asm volatile("cp.async.commit_group;" ::: "memory");
    asm volatile("cp.async.wait_group 0;" ::: "memory");
    __syncthreads();

    // ---- Q fragments in registers ----
    uint32_t qhf[8][4], qlf[8][4];
#pragma unroll
    for (int kt = 0; kt < 8; kt++) {
        int row = w * 16 + l8 + ((grp & 1) << 3);
        int ch  = 2 * kt + (grp >> 1);
        uint32_t off = row * 256 + ((((ch ^ row) & 7) | (ch & 8)) << 4);
        ldmx4(qhf[kt], sQh + off);
        ldmx4(qlf[kt], sQl + off);
    }
    __syncthreads();

    float of[16][4];
#pragma unroll
    for (int i = 0; i < 16; i++)
#pragma unroll
        for (int e = 0; e < 4; e++) of[i][e] = 0.f;
    float m0 = -1e30f, m1 = -1e30f, l0 = 0.f, l1 = 0.f;
    const int qpos0 = q0 + w * 16 + qd;
    const int qpos1 = qpos0 + 8;

    int kstart = q0 - (WINDOW - 1);
    if (kstart < 0) kstart = 0;
    const int kb0 = kstart & ~63;

    for (int kb = kb0; kb <= q0; kb += 64) {
        // ---- load K,V (h+l) ----
#pragma unroll
        for (int i = 0; i < 8; i++) {
            int cid = tid + 128 * i;
            int row = cid >> 4, c = cid & 15;
            uint32_t soff = row * 256 + ((((c ^ row) & 7) | (c & 8)) << 4);
            size_t goff = (size_t)(b * SEQ + kb + row) * KVD + kvh * HD + c * 8;
            cpasync16(sKh + soff, Kh + goff);
            cpasync16(sKl + soff, Kl + goff);
            cpasync16(sVh + soff, Vh + goff);
            cpasync16(sVl + soff, Vl + goff);
        }
        asm volatile("cp.async.commit_group;" ::: "memory");
        asm volatile("cp.async.wait_group 0;" ::: "memory");
        __syncthreads();

        // ---- S = Q K^T (3 split passes) ----
        float s[8][4];
#pragma unroll
        for (int nt = 0; nt < 8; nt++)
#pragma unroll
            for (int e = 0; e < 4; e++) s[nt][e] = 0.f;
#pragma unroll
        for (int kt = 0; kt < 8; kt++) {
            uint32_t bh[4][4], bl[4][4];
#pragma unroll
            for (int kg = 0; kg < 4; kg++) {
                int key = kg * 16 + l8 + ((grp >> 1) << 3);
                int ch  = 2 * kt + (grp & 1);
                uint32_t off = key * 256 + ((((ch ^ key) & 7) | (ch & 8)) << 4);
                ldmx4(bh[kg], sKh + off);
                ldmx4(bl[kg], sKl + off);
            }
#pragma unroll
            for (int nt = 0; nt < 8; nt++) {
                const uint32_t* ph = &bh[nt >> 1][(nt & 1) * 2];
                const uint32_t* pl = &bl[nt >> 1][(nt & 1) * 2];
                mma16816(s[nt], qhf[kt], ph);
                mma16816(s[nt], qhf[kt], pl);
                mma16816(s[nt], qlf[kt], ph);
            }
        }

        // ---- mask + scale + online softmax ----
        float bmax0 = -1e30f, bmax1 = -1e30f;
#pragma unroll
        for (int nt = 0; nt < 8; nt++) {
            int colb = kb + nt * 8 + ln4 * 2;
#pragma unroll
            for (int e = 0; e < 4; e++) {
                int col = colb + (e & 1);
                int qp  = (e < 2) ? qpos0 : qpos1;
                bool ok = (col <= qp) && (col > qp - WINDOW);
                s[nt][e] = ok ? s[nt][e] * scale : -1e30f;
            }
            bmax0 = fmaxf(bmax0, fmaxf(s[nt][0], s[nt][1]));
            bmax1 = fmaxf(bmax1, fmaxf(s[nt][2], s[nt][3]));
        }
        bmax0 = fmaxf(bmax0, __shfl_xor_sync(0xffffffffu, bmax0, 1));
        bmax0 = fmaxf(bmax0, __shfl_xor_sync(0xffffffffu, bmax0, 2));
        bmax1 = fmaxf(bmax1, __shfl_xor_sync(0xffffffffu, bmax1, 1));
        bmax1 = fmaxf(bmax1, __shfl_xor_sync(0xffffffffu, bmax1, 2));
        float mn0 = fmaxf(m0, bmax0), mn1 = fmaxf(m1, bmax1);
        bool dead0 = mn0 < -1e29f, dead1 = mn1 < -1e29f;
        float corr0 = dead0 ? 1.f : __expf(m0 - mn0);
        float corr1 = dead1 ? 1.f : __expf(m1 - mn1);
        float rs0 = 0.f, rs1 = 0.f;
#pragma unroll
        for (int nt = 0; nt < 8; nt++) {
            s[nt][0] = dead0 ? 0.f : __expf(s[nt][0] - mn0);
            s[nt][1] = dead0 ? 0.f : __expf(s[nt][1] - mn0);
            s[nt][2] = dead1 ? 0.f : __expf(s[nt][2] - mn1);
            s[nt][3] = dead1 ? 0.f : __expf(s[nt][3] - mn1);
            rs0 += s[nt][0] + s[nt][1];
            rs1 += s[nt][2] + s[nt][3];
        }
        rs0 += __shfl_xor_sync(0xffffffffu, rs0, 1);
        rs0 += __shfl_xor_sync(0xffffffffu, rs0, 2);
        rs1 += __shfl_xor_sync(0xffffffffu, rs1, 1);
        rs1 += __shfl_xor_sync(0xffffffffu, rs1, 2);
        l0 = l0 * corr0 + rs0;
        l1 = l1 * corr1 + rs1;
        m0 = mn0; m1 = mn1;
#pragma unroll
        for (int nt = 0; nt < 16; nt++) {
            of[nt][0] *= corr0; of[nt][1] *= corr0;
            of[nt][2] *= corr1; of[nt][3] *= corr1;
        }

        // ---- O += P V (3 split passes) ----
#pragma unroll
        for (int kt2 = 0; kt2 < 4; kt2++) {
            uint32_t pah[4], pal[4];
            split2(s[2 * kt2][0],     s[2 * kt2][1],     pah[0], pal[0]);
            split2(s[2 * kt2][2],     s[2 * kt2][3],     pah[1], pal[1]);
            split2(s[2 * kt2 + 1][0], s[2 * kt2 + 1][1], pah[2], pal[2]);
            split2(s[2 * kt2 + 1][2], s[2 * kt2 + 1][3], pah[3], pal[3]);
#pragma unroll
            for (int ntp = 0; ntp < 8; ntp++) {
                uint32_t vhf[4], vlf[4];
                int key = 16 * kt2 + l8 + ((grp & 1) << 3);
                int ch  = 2 * ntp + (grp >> 1);
                uint32_t off = key * 256 + ((((ch ^ key) & 7) | (ch & 8)) << 4);
                ldmx4t(vhf, sVh + off);
                ldmx4t(vlf, sVl + off);
                mma16816(of[2 * ntp],     pah, &vhf[0]);
                mma16816(of[2 * ntp],     pah, &vlf[0]);
                mma16816(of[2 * ntp],     pal, &vhf[0]);
                mma16816(of[2 * ntp + 1], pah, &vhf[2]);
                mma16816(of[2 * ntp + 1], pah, &vlf[2]);
                mma16816(of[2 * ntp + 1], pal, &vhf[2]);
            }
        }
        __syncthreads();   // all V reads done before next block's loads
    }

    // ---- epilogue: normalize, split, store ----
    float il0 = 1.f / l0, il1 = 1.f / l1;
    const int tok0 = b * SEQ + q0 + w * 16 + qd;
#pragma unroll
    for (int nt = 0; nt < 16; nt++) {
        int col = h * HD + nt * 8 + ln4 * 2;
        uint32_t hpk, lpk;
        split2(of[nt][0] * il0, of[nt][1] * il0, hpk, lpk);
        *(uint32_t*)(Oh + (size_t)tok0 * HIDDEN + col) = hpk;
        *(uint32_t*)(Ol + (size_t)tok0 * HIDDEN + col) = lpk;
        split2(of[nt][2] * il1, of[nt][3] * il1, hpk, lpk);
        *(uint32_t*)(Oh + (size_t)(tok0 + 8) * HIDDEN + col) = hpk;
        *(uint32_t*)(Ol + (size_t)(tok0 + 8) * HIDDEN + col) = lpk;
    }
}

// ---------------- launch ----------------------------------------------------------
extern "C" void kernel_launch(void* const* d_in, const int* in_sizes, int n_in,
                              void* d_out, int out_size)
{
    const float* hs = (const float*)d_in[0];
    const float* Wq = (const float*)d_in[2];
    const float* bq = (const float*)d_in[3];
    const float* Wk = (const float*)d_in[4];
    const float* bk = (const float*)d_in[5];
    const float* Wv = (const float*)d_in[6];
    const float* bv = (const float*)d_in[7];
    const float* Wo = (const float*)d_in[8];
    float* out = (float*)d_out;

    void *pq, *pk, *pv, *pxh, *pxl, *pqh, *pql, *pkh, *pkl, *pvh, *pvl;
    void *pwqh, *pwql, *pwkh, *pwkl, *pwvh, *pwvl, *pwoh, *pwol;
    cudaGetSymbolAddress(&pq, g_q);
    cudaGetSymbolAddress(&pk, g_k);
    cudaGetSymbolAddress(&pv, g_v);
    cudaGetSymbolAddress(&pxh, g_xh);
    cudaGetSymbolAddress(&pxl, g_xl);
    cudaGetSymbolAddress(&pqh, g_qh);
    cudaGetSymbolAddress(&pql, g_ql);
    cudaGetSymbolAddress(&pkh, g_kh);
    cudaGetSymbolAddress(&pkl, g_kl);
    cudaGetSymbolAddress(&pvh, g_vh);
    cudaGetSymbolAddress(&pvl, g_vl);
    cudaGetSymbolAddress(&pwqh, g_wqh);
    cudaGetSymbolAddress(&pwql, g_wql);
    cudaGetSymbolAddress(&pwkh, g_wkh);
    cudaGetSymbolAddress(&pwkl, g_wkl);
    cudaGetSymbolAddress(&pwvh, g_wvh);
    cudaGetSymbolAddress(&pwvl, g_wvl);
    cudaGetSymbolAddress(&pwoh, g_woh);
    cudaGetSymbolAddress(&pwol, g_wol);
    float* qb = (float*)pq;
    float* kb = (float*)pk;
    float* vb = (float*)pv;
    __nv_bfloat16* xh = (__nv_bfloat16*)pxh;
    __nv_bfloat16* xl = (__nv_bfloat16*)pxl;

    cudaFuncSetAttribute(gemm_mma, cudaFuncAttributeMaxDynamicSharedMemorySize, SMEM_GEMM);
    cudaFuncSetAttribute(flash_mma, cudaFuncAttributeMaxDynamicSharedMemorySize, FSMEM);

    const int n4h = MTOK * GK / 4;
    dim3 tb(32, 8);

    split_fp32<<<(n4h + 255) / 256, 256>>>((const float4*)hs, xh, xl, n4h);
    transp_split<<<dim3(HIDDEN / 32, GK / 32), tb>>>(Wq, (__nv_bfloat16*)pwqh, (__nv_bfloat16*)pwql, HIDDEN);
    transp_split<<<dim3(KVD / 32, GK / 32), tb>>>(Wk, (__nv_bfloat16*)pwkh, (__nv_bfloat16*)pwkl, KVD);
    transp_split<<<dim3(KVD / 32, GK / 32), tb>>>(Wv, (__nv_bfloat16*)pwvh, (__nv_bfloat16*)pwvl, KVD);
    transp_split<<<dim3(HIDDEN / 32, GK / 32), tb>>>(Wo, (__nv_bfloat16*)pwoh, (__nv_bfloat16*)pwol, HIDDEN);

    gemm_mma<<<dim3(HIDDEN / 128, MTOK / 128), 256, SMEM_GEMM>>>(
        xh, xl, (__nv_bfloat16*)pwqh, (__nv_bfloat16*)pwql, bq, qb, HIDDEN);
    gemm_mma<<<dim3(KVD / 128, MTOK / 128), 256, SMEM_GEMM>>>(
        xh, xl, (__nv_bfloat16*)pwkh, (__nv_bfloat16*)pwkl, bk, kb, KVD);
    gemm_mma<<<dim3(KVD / 128, MTOK / 128), 256, SMEM_GEMM>>>(
        xh, xl, (__nv_bfloat16*)pwvh, (__nv_bfloat16*)pwvl, bv, vb, KVD);

    rope_table<<<(SEQ * 64 + 255) / 256, 256>>>();
    {
        int total = MTOK * (NH + NKV) * 64;
        rope_split<<<(total + 255) / 256, 256>>>(
            qb, kb, (__nv_bfloat16*)pqh, (__nv_bfloat16*)pql,
            (__nv_bfloat16*)pkh, (__nv_bfloat16*)pkl);
    }
    {
        int n4v = MTOK * KVD / 4;
        split_fp32<<<(n4v + 255) / 256, 256>>>((const float4*)vb,
            (__nv_bfloat16*)pvh, (__nv_bfloat16*)pvl, n4v);
    }

    flash_mma<<<dim3(SEQ / 64, NH, BATCH), 128, FSMEM>>>(
        (__nv_bfloat16*)pqh, (__nv_bfloat16*)pql,
        (__nv_bfloat16*)pkh, (__nv_bfloat16*)pkl,
        (__nv_bfloat16*)pvh, (__nv_bfloat16*)pvl,
        xh, xl);   // attention output splits (overwrite hs splits)

    gemm_mma<<<dim3(HIDDEN / 128, MTOK / 128), 256, SMEM_GEMM>>>(
        xh, xl, (__nv_bfloat16*)pwoh, (__nv_bfloat16*)pwol, nullptr, out, HIDDEN);
}

// round 6
// speedup vs baseline: 9.7084x; 1.2767x over previous
#include <cuda_runtime.h>
#include <cuda_bf16.h>
#include <math.h>
#include <cstdint>

#define HIDDEN 2048
#define NH 16
#define NKV 4
#define HD 128
#define KVD 512
#define WINDOW 1024
#define BATCH 2
#define SEQ 2048
#define MTOK 4096
#define GK 2048

// ---------------- scratch (static device globals; no allocation) ----------------
__device__ __nv_bfloat16 g_xh[MTOK * GK], g_xl[MTOK * GK];          // act splits (hs, then attn out)
__device__ __nv_bfloat16 g_qb[MTOK * HIDDEN];                        // rotated Q (single bf16)
__device__ __nv_bfloat16 g_kb[MTOK * KVD];                           // rotated K (single bf16)
__device__ __nv_bfloat16 g_vh[MTOK * KVD], g_vl[MTOK * KVD];         // V splits
__device__ __nv_bfloat16 g_wqh[HIDDEN * GK], g_wql[HIDDEN * GK];
__device__ __nv_bfloat16 g_wkh[KVD * GK],    g_wkl[KVD * GK];
__device__ __nv_bfloat16 g_wvh[KVD * GK],    g_wvl[KVD * GK];
__device__ __nv_bfloat16 g_woh[HIDDEN * GK], g_wol[HIDDEN * GK];
__device__ float g_cos[SEQ * 64], g_sin[SEQ * 64];

// ---------------- helpers --------------------------------------------------------
__device__ __forceinline__ uint32_t smem_u32(const void* p) {
    uint32_t a;
    asm("{ .reg .u64 t; cvta.to.shared.u64 t, %1; cvt.u32.u64 %0, t; }" : "=r"(a) : "l"(p));
    return a;
}
__device__ __forceinline__ void ldmx4(uint32_t* r, uint32_t addr) {
    asm volatile("ldmatrix.sync.aligned.m8n8.x4.shared.b16 {%0,%1,%2,%3}, [%4];"
                 : "=r"(r[0]), "=r"(r[1]), "=r"(r[2]), "=r"(r[3]) : "r"(addr));
}
__device__ __forceinline__ void ldmx4t(uint32_t* r, uint32_t addr) {
    asm volatile("ldmatrix.sync.aligned.m8n8.x4.trans.shared.b16 {%0,%1,%2,%3}, [%4];"
                 : "=r"(r[0]), "=r"(r[1]), "=r"(r[2]), "=r"(r[3]) : "r"(addr));
}
__device__ __forceinline__ void mma16816(float* d, const uint32_t* a, const uint32_t* b) {
    asm volatile(
        "mma.sync.aligned.m16n8k16.row.col.f32.bf16.bf16.f32 "
        "{%0,%1,%2,%3}, {%4,%5,%6,%7}, {%8,%9}, {%0,%1,%2,%3};"
        : "+f"(d[0]), "+f"(d[1]), "+f"(d[2]), "+f"(d[3])
        : "r"(a[0]), "r"(a[1]), "r"(a[2]), "r"(a[3]), "r"(b[0]), "r"(b[1]));
}
__device__ __forceinline__ void split2(float a, float b, uint32_t& hpk, uint32_t& lpk) {
    asm("cvt.rn.bf16x2.f32 %0, %1, %2;" : "=r"(hpk) : "f"(b), "f"(a));
    float fa = __uint_as_float(hpk << 16);
    float fb = __uint_as_float(hpk & 0xffff0000u);
    float ra = a - fa, rb = b - fb;
    asm("cvt.rn.bf16x2.f32 %0, %1, %2;" : "=r"(lpk) : "f"(rb), "f"(ra));
}
__device__ __forceinline__ void cpasync16(uint32_t dst, const void* src) {
    asm volatile("cp.async.cg.shared.global [%0], [%1], 16;" :: "r"(dst), "l"(src) : "memory");
}

// ---------------- GEMM via mma.sync, templated passes + epilogue -----------------
// NT=2: single pass (Ah*Bh). NT=4: 3 split passes.
// EPI 0: fp32 store (+bias). EPI 1: rope + bf16 store (Q/K proj). EPI 2: split store (V proj).
template <int NT, int EPI>
__global__ __launch_bounds__(256, 1) void gemm_mma(
    const __nv_bfloat16* __restrict__ Ah, const __nv_bfloat16* __restrict__ Al,
    const __nv_bfloat16* __restrict__ Bh, const __nv_bfloat16* __restrict__ Bl,
    const float* __restrict__ bias, float* __restrict__ C,
    __nv_bfloat16* __restrict__ O1, __nv_bfloat16* __restrict__ O2, int N)
{
    extern __shared__ __align__(128) char smem[];
    const uint32_t sb = smem_u32(smem);
    const int tid  = threadIdx.x;
    const int lane = tid & 31;
    const int wid  = tid >> 5;
    const int wm   = wid >> 2;
    const int wn   = wid & 3;
    const int bn   = blockIdx.x * 128;
    const int bm   = blockIdx.y * 128;

    const int STAGE = NT * 16384;
    const int BHOFF = (NT == 2) ? 16384 : 32768;

    const __nv_bfloat16* srcs[NT];
    if (NT == 2) {
        srcs[0] = Ah + (size_t)bm * GK;
        srcs[1] = Bh + (size_t)bn * GK;
    } else {
        srcs[0] = Ah + (size_t)bm * GK;
        srcs[1] = Al + (size_t)bm * GK;
        srcs[2] = Bh + (size_t)bn * GK;
        srcs[3] = Bl + (size_t)bn * GK;
    }
    const int rr = tid >> 3, cc = tid & 7;

    const int idx8   = lane & 7;
    const int a_moff = ((lane >> 3) & 1) * 8;
    const int a_coff = lane >> 4;
    const int b_noff = (lane >> 4) * 8;
    const int b_coff = (lane >> 3) & 1;

    float acc[4][4][4];
#pragma unroll
    for (int i = 0; i < 4; i++)
#pragma unroll
        for (int j = 0; j < 4; j++)
#pragma unroll
            for (int e = 0; e < 4; e++) acc[i][j][e] = 0.f;

    auto issue = [&](int c, int buf) {
        const int k0 = c * 64;
        const uint32_t st = sb + buf * STAGE;
#pragma unroll
        for (int t = 0; t < NT; t++) {
            const __nv_bfloat16* bp = srcs[t] + k0 + cc * 8;
#pragma unroll
            for (int j = 0; j < 4; j++) {
                int r = rr + 32 * j;
                int byte = r * 128 + cc * 16;
                uint32_t dst = st + t * 16384 + (byte ^ ((byte >> 3) & 0x70));
                cpasync16(dst, bp + (size_t)r * GK);
            }
        }
        asm volatile("cp.async.commit_group;" ::: "memory");
    };

    issue(0, 0);
    issue(1, 1);
    issue(2, 2);

    for (int c = 0; c < 32; c++) {
        if (c <= 29)      asm volatile("cp.async.wait_group 2;" ::: "memory");
        else if (c == 30) asm volatile("cp.async.wait_group 1;" ::: "memory");
        else              asm volatile("cp.async.wait_group 0;" ::: "memory");
        __syncthreads();
        const uint32_t st = sb + (c % 3) * STAGE;

#pragma unroll
        for (int ks = 0; ks < 4; ks++) {
            uint32_t ah[4][4], al[4][4], bh[2][4], bl[2][4];
            const int chA = ks * 2 + a_coff;
            const int chB = ks * 2 + b_coff;
#pragma unroll
            for (int mt = 0; mt < 4; mt++) {
                int row = wm * 64 + mt * 16 + a_moff + idx8;
                uint32_t off = row * 128 + ((chA ^ (row & 7)) << 4);
                ldmx4(ah[mt], st + off);
                if (NT == 4) ldmx4(al[mt], st + 16384 + off);
            }
#pragma unroll
            for (int h = 0; h < 2; h++) {
                int row = wn * 32 + h * 16 + b_noff + idx8;
                uint32_t off = row * 128 + ((chB ^ (row & 7)) << 4);
                ldmx4(bh[h], st + BHOFF + off);
                if (NT == 4) ldmx4(bl[h], st + 49152 + off);
            }
#pragma unroll
            for (int mt = 0; mt < 4; mt++)
#pragma unroll
                for (int nt = 0; nt < 4; nt++) {
                    const uint32_t* ph = &bh[nt >> 1][(nt & 1) * 2];
                    mma16816(acc[mt][nt], ah[mt], ph);
                    if (NT == 4) {
                        const uint32_t* pl = &bl[nt >> 1][(nt & 1) * 2];
                        mma16816(acc[mt][nt], ah[mt], pl);
                        mma16816(acc[mt][nt], al[mt], ph);
                    }
                }
        }
        __syncthreads();
        if (c + 3 < 32) issue(c + 3, (c + 3) % 3);
    }

    const int r0   = wm * 64 + (lane >> 2);
    const int c0   = wn * 32 + (lane & 3) * 2;

    if (EPI == 0) {
#pragma unroll
        for (int mt = 0; mt < 4; mt++)
#pragma unroll
            for (int nt = 0; nt < 4; nt++) {
                int row = bm + r0 + mt * 16;
                int col = bn + c0 + nt * 8;
                float b0 = 0.f, b1 = 0.f;
                if (bias) { b0 = bias[col]; b1 = bias[col + 1]; }
                *(float2*)(C + (size_t)row * N + col)       = make_float2(acc[mt][nt][0] + b0, acc[mt][nt][1] + b1);
                *(float2*)(C + (size_t)(row + 8) * N + col) = make_float2(acc[mt][nt][2] + b0, acc[mt][nt][3] + b1);
            }
    } else if (EPI == 2) {
        // split to hi/lo bf16
#pragma unroll
        for (int mt = 0; mt < 4; mt++)
#pragma unroll
            for (int nt = 0; nt < 4; nt++) {
                int row = bm + r0 + mt * 16;
                int col = bn + c0 + nt * 8;
                float b0 = bias[col], b1 = bias[col + 1];
                uint32_t hpk, lpk;
                split2(acc[mt][nt][0] + b0, acc[mt][nt][1] + b1, hpk, lpk);
                *(uint32_t*)(O1 + (size_t)row * N + col) = hpk;
                *(uint32_t*)(O2 + (size_t)row * N + col) = lpk;
                split2(acc[mt][nt][2] + b0, acc[mt][nt][3] + b1, hpk, lpk);
                *(uint32_t*)(O1 + (size_t)(row + 8) * N + col) = hpk;
                *(uint32_t*)(O2 + (size_t)(row + 8) * N + col) = lpk;
            }
    } else {
        // EPI 1: rope + bf16; pairs (i, i+64) live in this 128-col block (one head).
        float* stile = (float*)smem;   // [128][132]
#pragma unroll
        for (int mt = 0; mt < 4; mt++)
#pragma unroll
            for (int nt = 0; nt < 4; nt++) {
                int rr2 = r0 + mt * 16;
                int cc2 = c0 + nt * 8;
                float b0 = bias[bn + cc2], b1 = bias[bn + cc2 + 1];
                stile[rr2 * 132 + cc2]           = acc[mt][nt][0] + b0;
                stile[rr2 * 132 + cc2 + 1]       = acc[mt][nt][1] + b1;
                stile[(rr2 + 8) * 132 + cc2]     = acc[mt][nt][2] + b0;
                stile[(rr2 + 8) * 132 + cc2 + 1] = acc[mt][nt][3] + b1;
            }
        __syncthreads();
#pragma unroll
        for (int j = 0; j < 32; j++) {
            int idx = tid + 256 * j;        // 8192 pairs
            int row = idx >> 6, i = idx & 63;
            int token = bm + row;
            int pos = token & (SEQ - 1);
            float cw = g_cos[pos * 64 + i], sw = g_sin[pos * 64 + i];
            float x1 = stile[row * 132 + i];
            float x2 = stile[row * 132 + i + 64];
            O1[(size_t)token * N + bn + i]      = __float2bfloat16(x1 * cw - x2 * sw);
            O1[(size_t)token * N + bn + i + 64] = __float2bfloat16(x2 * cw + x1 * sw);
        }
    }
}

// ---------------- fp32 -> bf16 hi/lo split ---------------------------------------
__global__ void split_fp32(const float4* __restrict__ X, __nv_bfloat16* __restrict__ H,
                           __nv_bfloat16* __restrict__ L, int n4)
{
    int i = blockIdx.x * blockDim.x + threadIdx.x;
    if (i >= n4) return;
    float4 v = X[i];
    float vv[4] = {v.x, v.y, v.z, v.w};
    uint32_t hp[2], lp[2];
#pragma unroll
    for (int p = 0; p < 2; p++)
        split2(vv[p * 2 + 0], vv[p * 2 + 1], hp[p], lp[p]);
    *(uint2*)(H + (size_t)i * 4) = make_uint2(hp[0], hp[1]);
    *(uint2*)(L + (size_t)i * 4) = make_uint2(lp[0], lp[1]);
}

// ---------------- W [2048,N] fp32 -> W^T [N,2048] bf16 hi/lo ----------------------
__global__ void transp_split(const float* __restrict__ W, __nv_bfloat16* __restrict__ H,
                             __nv_bfloat16* __restrict__ L, int N)
{
    __shared__ float t[32][33];
    int n0 = blockIdx.x * 32, k0 = blockIdx.y * 32;
    int tx = threadIdx.x, ty = threadIdx.y;
#pragma unroll
    for (int i = 0; i < 32; i += 8)
        t[ty + i][tx] = W[(size_t)(k0 + ty + i) * N + n0 + tx];
    __syncthreads();
#pragma unroll
    for (int i = 0; i < 32; i += 8) {
        float v = t[tx][ty + i];
        __nv_bfloat16 h = __float2bfloat16(v);
        __nv_bfloat16 l = __float2bfloat16(v - __bfloat162float(h));
        size_t o = (size_t)(n0 + ty + i) * GK + k0 + tx;
        H[o] = h; L[o] = l;
    }
}

// ---------------- RoPE cos/sin table (fp64, tiny) ---------------------------------
__global__ void rope_table()
{
    int idx = blockIdx.x * blockDim.x + threadIdx.x;
    if (idx >= SEQ * 64) return;
    int pos = idx >> 6, i = idx & 63;
    double ang = (double)pos * exp(-(double)i * (9.210340371976184 / 64.0));
    g_cos[idx] = (float)cos(ang);
    g_sin[idx] = (float)sin(ang);
}

// ---------------- Flash attention via mma.sync -----------------------------------
// Q,K single bf16 (S: 1 pass). V split (PV: 3 passes). 64 q-rows, 128 threads.
#define FSMEM (4 * 16384)

__global__ __launch_bounds__(128, 2) void flash_mma(
    const __nv_bfloat16* __restrict__ Q, const __nv_bfloat16* __restrict__ K,
    const __nv_bfloat16* __restrict__ Vh, const __nv_bfloat16* __restrict__ Vl,
    __nv_bfloat16* __restrict__ Oh, __nv_bfloat16* __restrict__ Ol)
{
    extern __shared__ __align__(128) char smem[];
    const uint32_t sb = smem_u32(smem);
    const uint32_t sQ = sb, sK = sb + 16384, sVh = sb + 32768, sVl = sb + 49152;
    const int qb = blockIdx.x, h = blockIdx.y, b = blockIdx.z;
    const int kvh = h >> 2;
    const int tid = threadIdx.x, lane = tid & 31, w = tid >> 5;
    const int q0 = qb * 64;
    const int l8 = lane & 7, grp = lane >> 3, qd = lane >> 2, ln4 = lane & 3;
    const float scale = 0.08838834764831845f;

    // ---- load Q tile ----
#pragma unroll
    for (int i = 0; i < 8; i++) {
        int cid = tid + 128 * i;
        int row = cid >> 4, c = cid & 15;
        uint32_t soff = row * 256 + ((((c ^ row) & 7) | (c & 8)) << 4);
        size_t goff = (size_t)(b * SEQ + q0 + row) * HIDDEN + h * HD + c * 8;
        cpasync16(sQ + soff, Q + goff);
    }
    asm volatile("cp.async.commit_group;" ::: "memory");
    asm volatile("cp.async.wait_group 0;" ::: "memory");
    __syncthreads();

    uint32_t qhf[8][4];
#pragma unroll
    for (int kt = 0; kt < 8; kt++) {
        int row = w * 16 + l8 + ((grp & 1) << 3);
        int ch  = 2 * kt + (grp >> 1);
        uint32_t off = row * 256 + ((((ch ^ row) & 7) | (ch & 8)) << 4);
        ldmx4(qhf[kt], sQ + off);
    }
    __syncthreads();

    float of[16][4];
#pragma unroll
    for (int i = 0; i < 16; i++)
#pragma unroll
        for (int e = 0; e < 4; e++) of[i][e] = 0.f;
    float m0 = -1e30f, m1 = -1e30f, l0 = 0.f, l1 = 0.f;
    const int qpos0 = q0 + w * 16 + qd;
    const int qpos1 = qpos0 + 8;

    int kstart = q0 - (WINDOW - 1);
    if (kstart < 0) kstart = 0;
    const int kb0 = kstart & ~63;

    for (int kb = kb0; kb <= q0; kb += 64) {
        // ---- load K, Vh, Vl ----
#pragma unroll
        for (int i = 0; i < 8; i++) {
            int cid = tid + 128 * i;
            int row = cid >> 4, c = cid & 15;
            uint32_t soff = row * 256 + ((((c ^ row) & 7) | (c & 8)) << 4);
            size_t goff = (size_t)(b * SEQ + kb + row) * KVD + kvh * HD + c * 8;
            cpasync16(sK + soff, K + goff);
            cpasync16(sVh + soff, Vh + goff);
            cpasync16(sVl + soff, Vl + goff);
        }
        asm volatile("cp.async.commit_group;" ::: "memory");
        asm volatile("cp.async.wait_group 0;" ::: "memory");
        __syncthreads();

        // ---- S = Q K^T (single pass) ----
        float s[8][4];
#pragma unroll
        for (int nt = 0; nt < 8; nt++)
#pragma unroll
            for (int e = 0; e < 4; e++) s[nt][e] = 0.f;
#pragma unroll
        for (int kt = 0; kt < 8; kt++) {
            uint32_t bh[4][4];
#pragma unroll
            for (int kg = 0; kg < 4; kg++) {
                int key = kg * 16 + l8 + ((grp >> 1) << 3);
                int ch  = 2 * kt + (grp & 1);
                uint32_t off = key * 256 + ((((ch ^ key) & 7) | (ch & 8)) << 4);
                ldmx4(bh[kg], sK + off);
            }
#pragma unroll
            for (int nt = 0; nt < 8; nt++)
                mma16816(s[nt], qhf[kt], &bh[nt >> 1][(nt & 1) * 2]);
        }

        // ---- mask + scale + online softmax ----
        float bmax0 = -1e30f, bmax1 = -1e30f;
#pragma unroll
        for (int nt = 0; nt < 8; nt++) {
            int colb = kb + nt * 8 + ln4 * 2;
#pragma unroll
            for (int e = 0; e < 4; e++) {
                int col = colb + (e & 1);
                int qp  = (e < 2) ? qpos0 : qpos1;
                bool ok = (col <= qp) && (col > qp - WINDOW);
                s[nt][e] = ok ? s[nt][e] * scale : -1e30f;
            }
            bmax0 = fmaxf(bmax0, fmaxf(s[nt][0], s[nt][1]));
            bmax1 = fmaxf(bmax1, fmaxf(s[nt][2], s[nt][3]));
        }
        bmax0 = fmaxf(bmax0, __shfl_xor_sync(0xffffffffu, bmax0, 1));
        bmax0 = fmaxf(bmax0, __shfl_xor_sync(0xffffffffu, bmax0, 2));
        bmax1 = fmaxf(bmax1, __shfl_xor_sync(0xffffffffu, bmax1, 1));
        bmax1 = fmaxf(bmax1, __shfl_xor_sync(0xffffffffu, bmax1, 2));
        float mn0 = fmaxf(m0, bmax0), mn1 = fmaxf(m1, bmax1);
        bool dead0 = mn0 < -1e29f, dead1 = mn1 < -1e29f;
        float corr0 = dead0 ? 1.f : __expf(m0 - mn0);
        float corr1 = dead1 ? 1.f : __expf(m1 - mn1);
        float rs0 = 0.f, rs1 = 0.f;
#pragma unroll
        for (int nt = 0; nt < 8; nt++) {
            s[nt][0] = dead0 ? 0.f : __expf(s[nt][0] - mn0);
            s[nt][1] = dead0 ? 0.f : __expf(s[nt][1] - mn0);
            s[nt][2] = dead1 ? 0.f : __expf(s[nt][2] - mn1);
            s[nt][3] = dead1 ? 0.f : __expf(s[nt][3] - mn1);
            rs0 += s[nt][0] + s[nt][1];
            rs1 += s[nt][2] + s[nt][3];
        }
        rs0 += __shfl_xor_sync(0xffffffffu, rs0, 1);
        rs0 += __shfl_xor_sync(0xffffffffu, rs0, 2);
        rs1 += __shfl_xor_sync(0xffffffffu, rs1, 1);
        rs1 += __shfl_xor_sync(0xffffffffu, rs1, 2);
        l0 = l0 * corr0 + rs0;
        l1 = l1 * corr1 + rs1;
        m0 = mn0; m1 = mn1;
#pragma unroll
        for (int nt = 0; nt < 16; nt++) {
            of[nt][0] *= corr0; of[nt][1] *= corr0;
            of[nt][2] *= corr1; of[nt][3] *= corr1;
        }

        // ---- O += P V (3 split passes) ----
#pragma unroll
        for (int kt2 = 0; kt2 < 4; kt2++) {
            uint32_t pah[4], pal[4];
            split2(s[2 * kt2][0],     s[2 * kt2][1],     pah[0], pal[0]);
            split2(s[2 * kt2][2],     s[2 * kt2][3],     pah[1], pal[1]);
            split2(s[2 * kt2 + 1][0], s[2 * kt2 + 1][1], pah[2], pal[2]);
            split2(s[2 * kt2 + 1][2], s[2 * kt2 + 1][3], pah[3], pal[3]);
#pragma unroll
            for (int ntp = 0; ntp < 8; ntp++) {
                uint32_t vhf[4], vlf[4];
                int key = 16 * kt2 + l8 + ((grp & 1) << 3);
                int ch  = 2 * ntp + (grp >> 1);
                uint32_t off = key * 256 + ((((ch ^ key) & 7) | (ch & 8)) << 4);
                ldmx4t(vhf, sVh + off);
                ldmx4t(vlf, sVl + off);
                mma16816(of[2 * ntp],     pah, &vhf[0]);
                mma16816(of[2 * ntp],     pah, &vlf[0]);
                mma16816(of[2 * ntp],     pal, &vhf[0]);
                mma16816(of[2 * ntp + 1], pah, &vhf[2]);
                mma16816(of[2 * ntp + 1], pah, &vlf[2]);
                mma16816(of[2 * ntp + 1], pal, &vhf[2]);
            }
        }
        __syncthreads();
    }

    // ---- epilogue: normalize, split, store ----
    float il0 = 1.f / l0, il1 = 1.f / l1;
    const int tok0 = b * SEQ + q0 + w * 16 + qd;
#pragma unroll
    for (int nt = 0; nt < 16; nt++) {
        int col = h * HD + nt * 8 + ln4 * 2;
        uint32_t hpk, lpk;
        split2(of[nt][0] * il0, of[nt][1] * il0, hpk, lpk);
        *(uint32_t*)(Oh + (size_t)tok0 * HIDDEN + col) = hpk;
        *(uint32_t*)(Ol + (size_t)tok0 * HIDDEN + col) = lpk;
        split2(of[nt][2] * il1, of[nt][3] * il1, hpk, lpk);
        *(uint32_t*)(Oh + (size_t)(tok0 + 8) * HIDDEN + col) = hpk;
        *(uint32_t*)(Ol + (size_t)(tok0 + 8) * HIDDEN + col) = lpk;
    }
}

// ---------------- launch ----------------------------------------------------------
extern "C" void kernel_launch(void* const* d_in, const int* in_sizes, int n_in,
                              void* d_out, int out_size)
{
    const float* hs = (const float*)d_in[0];
    const float* Wq = (const float*)d_in[2];
    const float* bq = (const float*)d_in[3];
    const float* Wk = (const float*)d_in[4];
    const float* bk = (const float*)d_in[5];
    const float* Wv = (const float*)d_in[6];
    const float* bv = (const float*)d_in[7];
    const float* Wo = (const float*)d_in[8];
    float* out = (float*)d_out;

    void *pxh, *pxl, *pqb, *pkb, *pvh, *pvl;
    void *pwqh, *pwql, *pwkh, *pwkl, *pwvh, *pwvl, *pwoh, *pwol;
    cudaGetSymbolAddress(&pxh, g_xh);
    cudaGetSymbolAddress(&pxl, g_xl);
    cudaGetSymbolAddress(&pqb, g_qb);
    cudaGetSymbolAddress(&pkb, g_kb);
    cudaGetSymbolAddress(&pvh, g_vh);
    cudaGetSymbolAddress(&pvl, g_vl);
    cudaGetSymbolAddress(&pwqh, g_wqh);
    cudaGetSymbolAddress(&pwql, g_wql);
    cudaGetSymbolAddress(&pwkh, g_wkh);
    cudaGetSymbolAddress(&pwkl, g_wkl);
    cudaGetSymbolAddress(&pwvh, g_wvh);
    cudaGetSymbolAddress(&pwvl, g_wvl);
    cudaGetSymbolAddress(&pwoh, g_woh);
    cudaGetSymbolAddress(&pwol, g_wol);
    __nv_bfloat16* xh = (__nv_bfloat16*)pxh;
    __nv_bfloat16* xl = (__nv_bfloat16*)pxl;

    const int SM1 = 3 * 2 * 16384;   // 96KB  (NT=2)
    const int SM3 = 3 * 4 * 16384;   // 192KB (NT=4)
    cudaFuncSetAttribute(gemm_mma<2, 1>, cudaFuncAttributeMaxDynamicSharedMemorySize, SM1);
    cudaFuncSetAttribute(gemm_mma<4, 2>, cudaFuncAttributeMaxDynamicSharedMemorySize, SM3);
    cudaFuncSetAttribute(gemm_mma<4, 0>, cudaFuncAttributeMaxDynamicSharedMemorySize, SM3);
    cudaFuncSetAttribute(flash_mma, cudaFuncAttributeMaxDynamicSharedMemorySize, FSMEM);

    const int n4h = MTOK * GK / 4;
    dim3 tb(32, 8);

    rope_table<<<(SEQ * 64 + 255) / 256, 256>>>();
    split_fp32<<<(n4h + 255) / 256, 256>>>((const float4*)hs, xh, xl, n4h);
    transp_split<<<dim3(HIDDEN / 32, GK / 32), tb>>>(Wq, (__nv_bfloat16*)pwqh, (__nv_bfloat16*)pwql, HIDDEN);
    transp_split<<<dim3(KVD / 32, GK / 32), tb>>>(Wk, (__nv_bfloat16*)pwkh, (__nv_bfloat16*)pwkl, KVD);
    transp_split<<<dim3(KVD / 32, GK / 32), tb>>>(Wv, (__nv_bfloat16*)pwvh, (__nv_bfloat16*)pwvl, KVD);
    transp_split<<<dim3(HIDDEN / 32, GK / 32), tb>>>(Wo, (__nv_bfloat16*)pwoh, (__nv_bfloat16*)pwol, HIDDEN);

    // Q, K projections: single-pass bf16, fused rope + bf16 store
    gemm_mma<2, 1><<<dim3(HIDDEN / 128, MTOK / 128), 256, SM1>>>(
        xh, nullptr, (__nv_bfloat16*)pwqh, nullptr, bq, nullptr,
        (__nv_bfloat16*)pqb, nullptr, HIDDEN);
    gemm_mma<2, 1><<<dim3(KVD / 128, MTOK / 128), 256, SM1>>>(
        xh, nullptr, (__nv_bfloat16*)pwkh, nullptr, bk, nullptr,
        (__nv_bfloat16*)pkb, nullptr, KVD);
    // V projection: 3-pass, fused hi/lo split store
    gemm_mma<4, 2><<<dim3(KVD / 128, MTOK / 128), 256, SM3>>>(
        xh, xl, (__nv_bfloat16*)pwvh, (__nv_bfloat16*)pwvl, bv, nullptr,
        (__nv_bfloat16*)pvh, (__nv_bfloat16*)pvl, KVD);

    // Flash attention -> attention-output splits (overwrite hs splits)
    flash_mma<<<dim3(SEQ / 64, NH, BATCH), 128, FSMEM>>>(
        (__nv_bfloat16*)pqb, (__nv_bfloat16*)pkb,
        (__nv_bfloat16*)pvh, (__nv_bfloat16*)pvl, xh, xl);

    // Output projection: 3-pass, fp32 store
    gemm_mma<4, 0><<<dim3(HIDDEN / 128, MTOK / 128), 256, SM3>>>(
        xh, xl, (__nv_bfloat16*)pwoh, (__nv_bfloat16*)pwol, nullptr, out,
        nullptr, nullptr, HIDDEN);
}